// round 10
// baseline (speedup 1.0000x reference)
#include <cuda_runtime.h>
#include <cuda_bf16.h>

#define B_DIM 512
#define P_DIM 512
#define F_DIM 1024
#define EPS_T 1e-8f

#define SPLITK 16
#define NTILES 64                   // 8x8 tiles of 64x64
#define NUNITS (NTILES * SPLITK)    // 1024
#define GRID_MAIN 296
#define QSCALE 65535.0f
#define KPITCH 72                   // smem row pitch in u16 (144B, conflict-free)

// Scratch (static device globals — no allocation allowed)
__device__ __align__(16) unsigned short g_qx[B_DIM * F_DIM];  // u16 sigmoid(x)
__device__ __align__(16) unsigned short g_qw[P_DIM * F_DIM];  // u16 sigmoid(w)
__device__ __align__(16) float g_S4[4][B_DIM + P_DIM];        // quarter row sums
__device__ float g_part[SPLITK * B_DIM * P_DIM];              // split-K partials
__device__ int   g_ctr;                                       // work counter
__device__ int   g_done[NTILES];                              // per-tile completion

// ---------------------------------------------------------------------------
// Kernel 1: sigmoid -> u16 quantize + quarter-row sums. Warp per quarter-row.
// grid 512 x 256. Also initializes g_ctr (=GRID_MAIN) and g_done (=0).
// ---------------------------------------------------------------------------
__global__ __launch_bounds__(256) void prep_kernel(
    const float* __restrict__ x, const float* __restrict__ w)
{
    if (blockIdx.x == 0) {
        if (threadIdx.x < NTILES) g_done[threadIdx.x] = 0;
        else if (threadIdx.x == NTILES) g_ctr = GRID_MAIN;
    }

    int warp = threadIdx.x >> 5;
    int lane = threadIdx.x & 31;
    int q = blockIdx.x * 8 + warp;        // 0..4095 quarter-row id
    int row = q >> 2;                     // 0..1023 combined row
    int quarter = q & 3;

    const float* src;
    unsigned short* dq;
    if (row < B_DIM) {
        src = x + (size_t)row * F_DIM;
        dq  = g_qx + (size_t)row * F_DIM;
    } else {
        src = w + (size_t)(row - B_DIM) * F_DIM;
        dq  = g_qw + (size_t)(row - B_DIM) * F_DIM;
    }

    int f4 = quarter * 64 + lane;
    float4 a = reinterpret_cast<const float4*>(src)[f4];
    float4 b = reinterpret_cast<const float4*>(src)[f4 + 32];

    float s0 = 1.0f / (1.0f + __expf(-a.x));
    float s1 = 1.0f / (1.0f + __expf(-a.y));
    float s2 = 1.0f / (1.0f + __expf(-a.z));
    float s3 = 1.0f / (1.0f + __expf(-a.w));
    float s4 = 1.0f / (1.0f + __expf(-b.x));
    float s5 = 1.0f / (1.0f + __expf(-b.y));
    float s6 = 1.0f / (1.0f + __expf(-b.z));
    float s7 = 1.0f / (1.0f + __expf(-b.w));

    unsigned q0 = __float2uint_rn(s0 * QSCALE);
    unsigned q1 = __float2uint_rn(s1 * QSCALE);
    unsigned q2 = __float2uint_rn(s2 * QSCALE);
    unsigned q3 = __float2uint_rn(s3 * QSCALE);
    unsigned q4 = __float2uint_rn(s4 * QSCALE);
    unsigned q5 = __float2uint_rn(s5 * QSCALE);
    unsigned q6 = __float2uint_rn(s6 * QSCALE);
    unsigned q7 = __float2uint_rn(s7 * QSCALE);
    reinterpret_cast<uint2*>(dq)[f4]      = make_uint2(q0 | (q1 << 16), q2 | (q3 << 16));
    reinterpret_cast<uint2*>(dq)[f4 + 32] = make_uint2(q4 | (q5 << 16), q6 | (q7 << 16));

    float local = ((s0 + s1) + (s2 + s3)) + ((s4 + s5) + (s6 + s7));
    #pragma unroll
    for (int o = 16; o > 0; o >>= 1)
        local += __shfl_xor_sync(0xFFFFFFFFu, local, o);
    if (lane == 0)
        g_S4[quarter][row] = local;
}

// ---------------------------------------------------------------------------
// Kernel 2: persistent u16 min-sum (vminu2 + dp2a), dynamic queue, and FUSED
// per-tile finalize: the CTA completing split 16/16 of a tile applies the
// Tversky epilogue for that tile (deterministic: fixed-order sum of fixed data).
// ---------------------------------------------------------------------------
__global__ __launch_bounds__(256, 2) void tversky_fused_kernel(
    const float* __restrict__ bias,
    const float* __restrict__ alpha,
    const float* __restrict__ beta,
    float* __restrict__ out)
{
    __shared__ unsigned short xs[2][64][KPITCH];
    __shared__ unsigned short ws[2][64][KPITCH];
    __shared__ int s_u, s_done;

    int tid = threadIdx.x;
    int tx = tid & 15;            // N: tx + 16j
    int ty = tid >> 4;            // M: ty + 16i
    int r0 = tid >> 3;            // loader row 0..31 (also r0+32)
    int seg = tid & 7;            // 16B segment

    const uint4* xg4 = reinterpret_cast<const uint4*>(g_qx);
    const uint4* wg4 = reinterpret_cast<const uint4*>(g_qw);

    int u = blockIdx.x;           // static first unit; g_ctr starts at GRID_MAIN

    {   // prologue: stage unit u into buf 0
        int tile = u >> 4, split = u & 15;
        int m0 = (tile >> 3) << 6, n0 = (tile & 7) << 6;
        int kb4 = split << 3;
        uint4 a0 = xg4[(m0 + r0) * 128 + kb4 + seg];
        uint4 a1 = xg4[(m0 + r0 + 32) * 128 + kb4 + seg];
        uint4 b0 = wg4[(n0 + r0) * 128 + kb4 + seg];
        uint4 b1 = wg4[(n0 + r0 + 32) * 128 + kb4 + seg];
        *reinterpret_cast<uint4*>(&xs[0][r0][seg * 8])      = a0;
        *reinterpret_cast<uint4*>(&xs[0][r0 + 32][seg * 8]) = a1;
        *reinterpret_cast<uint4*>(&ws[0][r0][seg * 8])      = b0;
        *reinterpret_cast<uint4*>(&ws[0][r0 + 32][seg * 8]) = b1;
    }
    int cur = 0;

    while (u < NUNITS) {
        if (tid == 0) s_u = atomicAdd(&g_ctr, 1);
        __syncthreads();          // staged tile + s_u visible
        int un = s_u;

        // prefetch next unit into registers (hidden behind compute)
        uint4 pa0, pa1, pb0, pb1;
        if (un < NUNITS) {
            int tile = un >> 4, split = un & 15;
            int m0 = (tile >> 3) << 6, n0 = (tile & 7) << 6;
            int kb4 = split << 3;
            pa0 = xg4[(m0 + r0) * 128 + kb4 + seg];
            pa1 = xg4[(m0 + r0 + 32) * 128 + kb4 + seg];
            pb0 = wg4[(n0 + r0) * 128 + kb4 + seg];
            pb1 = wg4[(n0 + r0 + 32) * 128 + kb4 + seg];
        }

        unsigned acc[4][4];
        #pragma unroll
        for (int i = 0; i < 4; i++)
            #pragma unroll
            for (int j = 0; j < 4; j++) acc[i][j] = 0u;

        {   // compute: 64 k of u16 per unit, 8 per chunk
            const unsigned short (*xb)[KPITCH] = xs[cur];
            const unsigned short (*wb)[KPITCH] = ws[cur];
            #pragma unroll 2
            for (int c = 0; c < 8; c++) {
                uint4 xq[4], wq[4];
                #pragma unroll
                for (int i = 0; i < 4; i++)
                    xq[i] = *reinterpret_cast<const uint4*>(&xb[ty + 16 * i][c * 8]);
                #pragma unroll
                for (int j = 0; j < 4; j++)
                    wq[j] = *reinterpret_cast<const uint4*>(&wb[tx + 16 * j][c * 8]);
                #pragma unroll
                for (int i = 0; i < 4; i++)
                    #pragma unroll
                    for (int j = 0; j < 4; j++) {
                        acc[i][j] = __dp2a_lo(__vminu2(xq[i].x, wq[j].x), 0x0101u, acc[i][j]);
                        acc[i][j] = __dp2a_lo(__vminu2(xq[i].y, wq[j].y), 0x0101u, acc[i][j]);
                        acc[i][j] = __dp2a_lo(__vminu2(xq[i].z, wq[j].z), 0x0101u, acc[i][j]);
                        acc[i][j] = __dp2a_lo(__vminu2(xq[i].w, wq[j].w), 0x0101u, acc[i][j]);
                    }
            }
        }

        if (un < NUNITS) {        // stage next unit into other buffer
            int nb = cur ^ 1;
            *reinterpret_cast<uint4*>(&xs[nb][r0][seg * 8])      = pa0;
            *reinterpret_cast<uint4*>(&xs[nb][r0 + 32][seg * 8]) = pa1;
            *reinterpret_cast<uint4*>(&ws[nb][r0][seg * 8])      = pb0;
            *reinterpret_cast<uint4*>(&ws[nb][r0 + 32][seg * 8]) = pb1;
        }

        int tile = u >> 4, split = u & 15;
        int m0 = (tile >> 3) << 6, n0 = (tile & 7) << 6;

        // write split-K partials (exact u32 counts as fp32)
        {
            float* pbase = g_part + ((size_t)split * B_DIM + m0) * P_DIM + n0;
            #pragma unroll
            for (int i = 0; i < 4; i++)
                #pragma unroll
                for (int j = 0; j < 4; j++)
                    pbase[(size_t)(ty + 16 * i) * P_DIM + tx + 16 * j] = (float)acc[i][j];
        }

        // completion ticket for this tile
        __threadfence();
        __syncthreads();
        if (tid == 0) s_done = atomicAdd(&g_done[tile], 1);
        __syncthreads();

        if (s_done == SPLITK - 1) {
            // this CTA finalizes tile: out = I/(I + a(Sx-I) + b(Sw-I) + eps) + bias
            __threadfence();
            int fx = tid & 15;                 // float4 column 0..15
            int rg = tid >> 4;                 // row group 0..15 (4 rows each)
            float av = *alpha;
            float bv = *beta;
            float4 bs = *reinterpret_cast<const float4*>(bias + n0 + fx * 4);

            float4 Sw = make_float4(0.f, 0.f, 0.f, 0.f);
            #pragma unroll
            for (int qt = 0; qt < 4; qt++) {
                float4 v = *reinterpret_cast<const float4*>(&g_S4[qt][B_DIM + n0 + fx * 4]);
                Sw.x += v.x; Sw.y += v.y; Sw.z += v.z; Sw.w += v.w;
            }

            const float inv = 1.0f / QSCALE;
            #pragma unroll
            for (int rr = 0; rr < 4; rr++) {
                int m = m0 + rg * 4 + rr;
                const float4* pp = reinterpret_cast<const float4*>(g_part)
                                 + (size_t)m * (P_DIM / 4) + (n0 / 4) + fx;
                float4 I = make_float4(0.f, 0.f, 0.f, 0.f);
                #pragma unroll
                for (int s = 0; s < SPLITK; s++) {
                    float4 v = __ldcg(pp + (size_t)s * (B_DIM * P_DIM / 4));
                    I.x += v.x; I.y += v.y; I.z += v.z; I.w += v.w;
                }
                I.x *= inv; I.y *= inv; I.z *= inv; I.w *= inv;

                float Sx = g_S4[0][m] + g_S4[1][m] + g_S4[2][m] + g_S4[3][m];

                float4 o;
                o.x = I.x / (I.x + av * (Sx - I.x) + bv * (Sw.x - I.x) + EPS_T) + bs.x;
                o.y = I.y / (I.y + av * (Sx - I.y) + bv * (Sw.y - I.y) + EPS_T) + bs.y;
                o.z = I.z / (I.z + av * (Sx - I.z) + bv * (Sw.z - I.z) + EPS_T) + bs.z;
                o.w = I.w / (I.w + av * (Sx - I.w) + bv * (Sw.w - I.w) + EPS_T) + bs.w;
                *reinterpret_cast<float4*>(out + (size_t)m * P_DIM + n0 + fx * 4) = o;
            }
        }

        u = un;
        cur ^= 1;
        __syncthreads();          // protect s_u/s_done + smem buffer reuse
    }
}

// ---------------------------------------------------------------------------
extern "C" void kernel_launch(void* const* d_in, const int* in_sizes, int n_in,
                              void* d_out, int out_size)
{
    const float* x      = (const float*)d_in[0];   // (512, 1024)
    const float* weight = (const float*)d_in[1];   // (512, 1024)
    const float* bias   = (const float*)d_in[2];   // (512,)
    const float* alpha  = (const float*)d_in[3];   // scalar
    const float* beta   = (const float*)d_in[4];   // scalar
    float* out = (float*)d_out;                    // (512, 512)

    prep_kernel<<<512, 256>>>(x, weight);
    tversky_fused_kernel<<<GRID_MAIN, 256>>>(bias, alpha, beta, out);
}

// round 11
// speedup vs baseline: 1.4857x; 1.4857x over previous
#include <cuda_runtime.h>
#include <cuda_bf16.h>

#define B_DIM 512
#define P_DIM 512
#define F_DIM 1024
#define EPS_T 1e-8f

#define SPLITK 16
#define NTILES 64                   // 8x8 tiles of 64x64
#define NUNITS (NTILES * SPLITK)    // 1024
#define GRID_MAIN 444               // 3 CTAs/SM x 148
#define QSCALE 65535.0f
#define KPITCH 72                   // smem row pitch in u16 (144B)

// Scratch (static device globals — no allocation allowed)
__device__ __align__(16) unsigned short g_qx[B_DIM * F_DIM];  // u16 sigmoid(x)
__device__ __align__(16) unsigned short g_qw[P_DIM * F_DIM];  // u16 sigmoid(w)
__device__ __align__(16) float g_S[B_DIM + P_DIM];            // fp32 row sums
__device__ float g_part[SPLITK * B_DIM * P_DIM];              // split-K partials
__device__ int   g_ctr;                                       // work counter

// ---------------------------------------------------------------------------
__device__ __forceinline__ float sigmoid_fast(float x)
{
    float t;
    asm("tanh.approx.f32 %0, %1;" : "=f"(t) : "f"(x * 0.5f));
    return fmaf(0.5f, t, 0.5f);
}

__device__ __forceinline__ void cp16(void* smem_dst, const void* gsrc)
{
    unsigned sdst = (unsigned)__cvta_generic_to_shared(smem_dst);
    asm volatile("cp.async.cg.shared.global [%0], [%1], 16;"
                 :: "r"(sdst), "l"(gsrc));
}

// ---------------------------------------------------------------------------
// Kernel 1: sigmoid (1 MUFU via tanh.approx) -> u16 quantize + row sums.
// One block per row, 1024 x 256. Also resets g_ctr to GRID_MAIN.
// ---------------------------------------------------------------------------
__global__ __launch_bounds__(256) void prep_kernel(
    const float* __restrict__ x, const float* __restrict__ w)
{
    if (blockIdx.x == 0 && threadIdx.x == 0) g_ctr = GRID_MAIN;

    int row = blockIdx.x;                 // 0..1023 combined
    int tid = threadIdx.x;

    const float* src;
    unsigned short* dq;
    if (row < B_DIM) {
        src = x + (size_t)row * F_DIM;
        dq  = g_qx + (size_t)row * F_DIM;
    } else {
        src = w + (size_t)(row - B_DIM) * F_DIM;
        dq  = g_qw + (size_t)(row - B_DIM) * F_DIM;
    }

    float4 v = reinterpret_cast<const float4*>(src)[tid];
    float s0 = sigmoid_fast(v.x);
    float s1 = sigmoid_fast(v.y);
    float s2 = sigmoid_fast(v.z);
    float s3 = sigmoid_fast(v.w);

    unsigned q0 = __float2uint_rn(s0 * QSCALE);
    unsigned q1 = __float2uint_rn(s1 * QSCALE);
    unsigned q2 = __float2uint_rn(s2 * QSCALE);
    unsigned q3 = __float2uint_rn(s3 * QSCALE);
    reinterpret_cast<uint2*>(dq)[tid] = make_uint2(q0 | (q1 << 16), q2 | (q3 << 16));

    float local = (s0 + s1) + (s2 + s3);
    #pragma unroll
    for (int o = 16; o > 0; o >>= 1)
        local += __shfl_xor_sync(0xFFFFFFFFu, local, o);

    __shared__ float red[8];
    if ((tid & 31) == 0) red[tid >> 5] = local;
    __syncthreads();
    if (tid == 0) {
        float t = 0.f;
        #pragma unroll
        for (int i = 0; i < 8; i++) t += red[i];
        g_S[row] = t;
    }
}

// ---------------------------------------------------------------------------
// Kernel 2: persistent u16 min-sum (vminu2 + dp2a), dynamic queue,
// cp.async double-buffered staging, ONE barrier per unit.
// Unit = 64x64 tile x KC=64 k. 1024 units, grid 444 x 256, 3 CTAs/SM.
// ---------------------------------------------------------------------------
__global__ __launch_bounds__(256, 3) void tversky_main_kernel()
{
    __shared__ __align__(16) unsigned short xs[2][64][KPITCH];
    __shared__ __align__(16) unsigned short ws[2][64][KPITCH];
    __shared__ int s_uu[2];

    int tid = threadIdx.x;
    int tx = tid & 15;            // N: tx + 16j
    int ty = tid >> 4;            // M: ty + 16i
    int r0 = tid >> 3;            // loader row 0..31 (also r0+32)
    int seg = tid & 7;            // 16B segment

    const uint4* xg4 = reinterpret_cast<const uint4*>(g_qx);
    const uint4* wg4 = reinterpret_cast<const uint4*>(g_qw);

    int u = blockIdx.x;           // static first unit; g_ctr starts at GRID_MAIN
    int cur = 0;

    {   // prologue: stage unit u into buf 0 via cp.async
        int tile = u >> 4, split = u & 15;
        int m0 = (tile >> 3) << 6, n0 = (tile & 7) << 6;
        int kb4 = split << 3;
        cp16(&xs[0][r0][seg * 8],      xg4 + (m0 + r0) * 128 + kb4 + seg);
        cp16(&xs[0][r0 + 32][seg * 8], xg4 + (m0 + r0 + 32) * 128 + kb4 + seg);
        cp16(&ws[0][r0][seg * 8],      wg4 + (n0 + r0) * 128 + kb4 + seg);
        cp16(&ws[0][r0 + 32][seg * 8], wg4 + (n0 + r0 + 32) * 128 + kb4 + seg);
        asm volatile("cp.async.commit_group;" ::: "memory");
    }

    while (u < NUNITS) {
        if (tid == 0) s_uu[cur] = atomicAdd(&g_ctr, 1);
        asm volatile("cp.async.wait_group 0;" ::: "memory");
        __syncthreads();          // buf(cur) complete everywhere; s_uu[cur] visible
        int un = s_uu[cur];

        if (un < NUNITS) {        // stage next unit into other buffer (async)
            int tile = un >> 4, split = un & 15;
            int m0 = (tile >> 3) << 6, n0 = (tile & 7) << 6;
            int kb4 = split << 3;
            int nb = cur ^ 1;
            cp16(&xs[nb][r0][seg * 8],      xg4 + (m0 + r0) * 128 + kb4 + seg);
            cp16(&xs[nb][r0 + 32][seg * 8], xg4 + (m0 + r0 + 32) * 128 + kb4 + seg);
            cp16(&ws[nb][r0][seg * 8],      wg4 + (n0 + r0) * 128 + kb4 + seg);
            cp16(&ws[nb][r0 + 32][seg * 8], wg4 + (n0 + r0 + 32) * 128 + kb4 + seg);
            asm volatile("cp.async.commit_group;" ::: "memory");
        }

        unsigned acc[4][4];
        #pragma unroll
        for (int i = 0; i < 4; i++)
            #pragma unroll
            for (int j = 0; j < 4; j++) acc[i][j] = 0u;

        {   // compute: 64 k of u16 per unit, 8 per chunk
            const unsigned short (*xb)[KPITCH] = xs[cur];
            const unsigned short (*wb)[KPITCH] = ws[cur];
            #pragma unroll 2
            for (int c = 0; c < 8; c++) {
                uint4 xq[4], wq[4];
                #pragma unroll
                for (int i = 0; i < 4; i++)
                    xq[i] = *reinterpret_cast<const uint4*>(&xb[ty + 16 * i][c * 8]);
                #pragma unroll
                for (int j = 0; j < 4; j++)
                    wq[j] = *reinterpret_cast<const uint4*>(&wb[tx + 16 * j][c * 8]);
                #pragma unroll
                for (int i = 0; i < 4; i++)
                    #pragma unroll
                    for (int j = 0; j < 4; j++) {
                        acc[i][j] = __dp2a_lo(__vminu2(xq[i].x, wq[j].x), 0x0101u, acc[i][j]);
                        acc[i][j] = __dp2a_lo(__vminu2(xq[i].y, wq[j].y), 0x0101u, acc[i][j]);
                        acc[i][j] = __dp2a_lo(__vminu2(xq[i].z, wq[j].z), 0x0101u, acc[i][j]);
                        acc[i][j] = __dp2a_lo(__vminu2(xq[i].w, wq[j].w), 0x0101u, acc[i][j]);
                    }
            }
        }

        // write split-K partials for unit u (exact u32 counts as fp32)
        {
            int tile = u >> 4, split = u & 15;
            int m0 = (tile >> 3) << 6, n0 = (tile & 7) << 6;
            float* pbase = g_part + ((size_t)split * B_DIM + m0) * P_DIM + n0;
            #pragma unroll
            for (int i = 0; i < 4; i++)
                #pragma unroll
                for (int j = 0; j < 4; j++)
                    pbase[(size_t)(ty + 16 * i) * P_DIM + tx + 16 * j] = (float)acc[i][j];
        }

        u = un;
        cur ^= 1;
        // no trailing barrier needed: next iteration's wait+sync precedes any
        // write into the buffer just consumed, and s_uu is parity-buffered.
    }
}

// ---------------------------------------------------------------------------
// Kernel 3: combine 16 split-K partials (scale 1/65535) + Tversky epilogue.
//   out = I / (I + alpha*(Sx-I) + beta*(Sw-I) + eps) + bias
// ---------------------------------------------------------------------------
__global__ __launch_bounds__(256) void finalize_kernel(
    const float* __restrict__ bias,
    const float* __restrict__ alpha,
    const float* __restrict__ beta,
    float* __restrict__ out)
{
    int t4 = blockIdx.x * 256 + threadIdx.x;   // float4 id, 0..65535
    int m  = t4 >> 7;
    int n4 = t4 & 127;

    const float4* pp = reinterpret_cast<const float4*>(g_part) + t4;
    float4 I = make_float4(0.f, 0.f, 0.f, 0.f);
    #pragma unroll
    for (int s = 0; s < SPLITK; s++) {
        float4 v = pp[(size_t)s * (B_DIM * P_DIM / 4)];
        I.x += v.x; I.y += v.y; I.z += v.z; I.w += v.w;
    }
    const float inv = 1.0f / QSCALE;
    I.x *= inv; I.y *= inv; I.z *= inv; I.w *= inv;

    float Sx = g_S[m];
    float4 Sw = reinterpret_cast<const float4*>(g_S + B_DIM)[n4];

    float a = *alpha;
    float b = *beta;
    float4 bs = reinterpret_cast<const float4*>(bias)[n4];

    float4 o;
    o.x = I.x / (I.x + a * (Sx - I.x) + b * (Sw.x - I.x) + EPS_T) + bs.x;
    o.y = I.y / (I.y + a * (Sx - I.y) + b * (Sw.y - I.y) + EPS_T) + bs.y;
    o.z = I.z / (I.z + a * (Sx - I.z) + b * (Sw.z - I.z) + EPS_T) + bs.z;
    o.w = I.w / (I.w + a * (Sx - I.w) + b * (Sw.w - I.w) + EPS_T) + bs.w;

    reinterpret_cast<float4*>(out)[t4] = o;
}

// ---------------------------------------------------------------------------
extern "C" void kernel_launch(void* const* d_in, const int* in_sizes, int n_in,
                              void* d_out, int out_size)
{
    const float* x      = (const float*)d_in[0];   // (512, 1024)
    const float* weight = (const float*)d_in[1];   // (512, 1024)
    const float* bias   = (const float*)d_in[2];   // (512,)
    const float* alpha  = (const float*)d_in[3];   // scalar
    const float* beta   = (const float*)d_in[4];   // scalar
    float* out = (float*)d_out;                    // (512, 512)

    prep_kernel<<<B_DIM + P_DIM, 256>>>(x, weight);
    tversky_main_kernel<<<GRID_MAIN, 256>>>();
    finalize_kernel<<<(B_DIM * P_DIM / 4) / 256, 256>>>(bias, alpha, beta, out);
}